// round 3
// baseline (speedup 1.0000x reference)
#include <cuda_runtime.h>
#include <cuda_bf16.h>

// Problem constants
#define B_   64
#define L_   32
#define D_   64
#define V_   100000
#define TIN  8
#define THID 128
#define R_   2048          // B*L rows
#define LOSS_T 29          // t < 29 -> loss rows, t >= 29 -> topk rows

// ---------------- scratch (__device__ globals: allowed) ----------------
__device__ float g_time_emb[R_ * D_];
__device__ float g_x[R_ * D_];
__device__ float g_seq[R_ * D_];
__device__ float g_lt[R_];
__device__ float g_mom[R_ * 4];   // loss rows: m1,m2,m3 ; topk rows: slot0 = gt-count

// ---------------- fast exp on FMA pipe ----------------
__device__ __forceinline__ float fexp(float x) {
    float t = x * 1.4426950408889634f;
    float z = t + 12582912.0f;                 // round-to-nearest via magic add
    int   n = __float_as_int(z) - 0x4B400000;
    float r = t - (z - 12582912.0f);           // r in [-0.5, 0.5]
    // 2^r Taylor, degree 6: max rel err ~1.2e-7
    float p = fmaf(1.5403530e-4f, r, 1.3333558e-3f);
    p = fmaf(p, r, 9.6181291e-3f);
    p = fmaf(p, r, 5.5504109e-2f);
    p = fmaf(p, r, 2.4022651e-1f);
    p = fmaf(p, r, 6.9314718e-1f);
    p = fmaf(p, r, 1.0f);
    return __int_as_float((n + 127) << 23) * p;
}

__device__ __forceinline__ void ffma2(unsigned long long& d,
                                      unsigned long long a,
                                      unsigned long long b) {
    asm("fma.rn.f32x2 %0, %1, %2, %0;" : "+l"(d) : "l"(a), "l"(b));
}

// ---------------- K1: time MLP + venue gather -> time_emb, x ----------------
__global__ void k_embed(const float* __restrict__ time, const int* __restrict__ venue,
                        const float* __restrict__ vt,
                        const float* __restrict__ w1, const float* __restrict__ b1,
                        const float* __restrict__ w2, const float* __restrict__ b2) {
    int row = blockIdx.x;          // 0..2047
    int tid = threadIdx.x;         // 0..127
    __shared__ float ts[TIN];
    __shared__ float hid[THID];
    if (tid < TIN) ts[tid] = time[row * TIN + tid];
    __syncthreads();
    float a = b1[tid];
#pragma unroll
    for (int k = 0; k < TIN; k++) a = fmaf(ts[k], w1[k * THID + tid], a);
    hid[tid] = fmaxf(a, 0.f);
    __syncthreads();
    if (tid < D_) {
        float te = b2[tid];
#pragma unroll 16
        for (int j = 0; j < THID; j++) te = fmaf(hid[j], w2[j * D_ + tid], te);
        g_time_emb[row * D_ + tid] = te;
        int vv = venue[row];
        g_x[row * D_ + tid] = vt[vv * D_ + tid] + te;
    }
}

// ---------------- K2: RNN over all 32 steps -> g_seq (h_before - time_emb) ----------------
__global__ void k_rnn(const int* __restrict__ user, const float* __restrict__ user_table,
                      const float* __restrict__ Wih, const float* __restrict__ Whh,
                      const float* __restrict__ bih, const float* __restrict__ bhh) {
    int b = blockIdx.x;            // 0..63
    int tid = threadIdx.x;         // 0..63
    __shared__ float WihT[D_ * D_];
    __shared__ float WhhT[D_ * D_];
    __shared__ float h[D_];
    __shared__ float xs[D_];
    for (int i = 0; i < D_; i++) {
        WihT[i * D_ + tid] = Wih[tid * D_ + i];
        WhhT[i * D_ + tid] = Whh[tid * D_ + i];
    }
    h[tid] = user_table[user[b] * D_ + tid];
    float bias = bih[tid] + bhh[tid];
    __syncthreads();
    for (int t = 0; t < L_; t++) {
        int r = b * L_ + t;
        g_seq[r * D_ + tid] = h[tid] - g_time_emb[r * D_ + tid];
        xs[tid] = g_x[r * D_ + tid];
        __syncthreads();
        float a = bias;
#pragma unroll 16
        for (int k = 0; k < D_; k++)
            a = fmaf(xs[k], WihT[k * D_ + tid], fmaf(h[k], WhhT[k * D_ + tid], a));
        __syncthreads();
        h[tid] = tanhf(a);
        __syncthreads();
    }
}

// ---------------- K3: target logits + zero moments ----------------
__global__ void k_target(const int* __restrict__ venue, const float* __restrict__ vt) {
    int r = blockIdx.x;            // 0..2047
    int tid = threadIdx.x;         // 0..63
    if (tid < 4) g_mom[r * 4 + tid] = 0.f;
    int tgt = venue[r];
    float v = g_seq[r * D_ + tid] * vt[tgt * D_ + tid];
#pragma unroll
    for (int o = 16; o; o >>= 1) v += __shfl_down_sync(0xffffffffu, v, o);
    __shared__ float p2[2];
    if ((tid & 31) == 0) p2[tid >> 5] = v;
    __syncthreads();
    if (tid == 0) g_lt[r] = p2[0] + p2[1];
}

// ---------------- K4: main pass — fused GEMM + softmax moments + rank counts ----------------
#define VT 128
#define VCHUNK 4352            // 34 tiles of 128
#define NVCH 23                // ceil(100000/4352)

__global__ void __launch_bounds__(256, 2)
k_main(const float* __restrict__ vt, const int* __restrict__ venue) {
    __shared__ __align__(16) float  venT[D_ * VT];       // [k][v]  32 KB
    __shared__ __align__(16) float2 seqDup[D_ * 32];     // [k][r] dup  16 KB
    const int tx  = threadIdx.x;      // 0..31
    const int ty  = threadIdx.y;      // 0..7
    const int tid = ty * 32 + tx;
    const int row0 = blockIdx.y * 32;                     // one batch b
    const int vstart = blockIdx.x * VCHUNK;
    const int vend   = min(V_, vstart + VCHUNK);

    // load seq tile (k-major, duplicated pairs for f32x2)
    for (int e = tid; e < D_ * 32; e += 256) {
        int r = e & 31, k = e >> 5;
        float s = g_seq[(row0 + r) * D_ + k];
        seqDup[k * 32 + r] = make_float2(s, s);
    }
    // per-row metadata (4 rows per thread: t = 4*ty + i)
    float thr[4]; int tgtv[4]; bool istop[4];
    float mom[4][3]; float cnt[4];
#pragma unroll
    for (int i = 0; i < 4; i++) {
        int t = 4 * ty + i;
        int r = row0 + t;
        thr[i] = g_lt[r]; tgtv[i] = venue[r]; istop[i] = (t >= LOSS_T);
        mom[i][0] = mom[i][1] = mom[i][2] = 0.f; cnt[i] = 0.f;
    }
    __syncthreads();

    const ulonglong2* venp = reinterpret_cast<const ulonglong2*>(venT);
    const ulonglong2* seqp = reinterpret_cast<const ulonglong2*>(seqDup);

    for (int vbase = vstart; vbase < vend; vbase += VT) {
        // load venue tile transposed: element e = k*128 + vl (smem-coalesced writes)
        for (int e = tid; e < D_ * VT; e += 256) {
            int vl = e & (VT - 1), k = e >> 7;
            int v = vbase + vl;
            venT[e] = (v < V_) ? vt[v * D_ + k] : 0.f;
        }
        __syncthreads();

        unsigned long long acc[4][2];
#pragma unroll
        for (int i = 0; i < 4; i++) { acc[i][0] = 0ull; acc[i][1] = 0ull; }

#pragma unroll 16
        for (int k = 0; k < D_; k++) {
            ulonglong2 vv = venp[k * 32 + tx];            // venues 4tx..4tx+3 (2 pairs)
            ulonglong2 sA = seqp[k * 16 + 2 * ty];        // rows 4ty, 4ty+1 (dup)
            ulonglong2 sB = seqp[k * 16 + 2 * ty + 1];    // rows 4ty+2, 4ty+3 (dup)
            ffma2(acc[0][0], sA.x, vv.x); ffma2(acc[0][1], sA.x, vv.y);
            ffma2(acc[1][0], sA.y, vv.x); ffma2(acc[1][1], sA.y, vv.y);
            ffma2(acc[2][0], sB.x, vv.x); ffma2(acc[2][1], sB.x, vv.y);
            ffma2(acc[3][0], sB.y, vv.x); ffma2(acc[3][1], sB.y, vv.y);
        }

        int v0 = vbase + 4 * tx;
#pragma unroll
        for (int i = 0; i < 4; i++) {
            float l[4];
            l[0] = __uint_as_float((unsigned)(acc[i][0]));
            l[1] = __uint_as_float((unsigned)(acc[i][0] >> 32));
            l[2] = __uint_as_float((unsigned)(acc[i][1]));
            l[3] = __uint_as_float((unsigned)(acc[i][1] >> 32));
            if (istop[i]) {
#pragma unroll
                for (int j = 0; j < 4; j++)
                    if (v0 + j < V_ && v0 + j != tgtv[i] && l[j] > thr[i]) cnt[i] += 1.f;
            } else {
#pragma unroll
                for (int j = 0; j < 4; j++) {
                    if (v0 + j < V_) {
                        float e1 = fexp(l[j]);
                        float e2 = e1 * e1;
                        mom[i][0] += e1; mom[i][1] += e2; mom[i][2] += e2 * e1;
                    }
                }
            }
        }
        __syncthreads();
    }

    // warp reduce (all lanes of a warp share the same 4 rows)
#pragma unroll
    for (int i = 0; i < 4; i++) {
        float m0 = mom[i][0], m1 = mom[i][1], m2 = mom[i][2], c = cnt[i];
#pragma unroll
        for (int o = 16; o; o >>= 1) {
            m0 += __shfl_down_sync(0xffffffffu, m0, o);
            m1 += __shfl_down_sync(0xffffffffu, m1, o);
            m2 += __shfl_down_sync(0xffffffffu, m2, o);
            c  += __shfl_down_sync(0xffffffffu, c,  o);
        }
        if (tx == 0) {
            int r = row0 + 4 * ty + i;
            if (istop[i]) {
                atomicAdd(&g_mom[r * 4 + 0], c);
            } else {
                atomicAdd(&g_mom[r * 4 + 0], m0);
                atomicAdd(&g_mom[r * 4 + 1], m1);
                atomicAdd(&g_mom[r * 4 + 2], m2);
            }
        }
    }
}

// ---------------- K5: finalize loss + counts ----------------
__global__ void k_final(float* __restrict__ out) {
    int tid = threadIdx.x;   // 256
    float loss = 0.f, c1 = 0.f, c5 = 0.f, c10 = 0.f, c20 = 0.f;
    for (int r = tid; r < R_; r += 256) {
        int t = r & 31;
        if (t < LOSS_T) {
            float s1 = g_mom[r * 4 + 0];
            float m2 = g_mom[r * 4 + 1];
            float m3 = g_mom[r * 4 + 2];
            float pt = fexp(g_lt[r]) / s1;
            float is1 = 1.f / s1;
            // sum_v exp(p_v) = V + 1 + m2/(2 s1^2) + m3/(6 s1^3) + O(1/4!)
            float S = (float)V_ + 1.0f
                    + m2 * is1 * is1 * 0.5f
                    + m3 * is1 * is1 * is1 * (1.0f / 6.0f);
            loss += (logf(S) - pt);
        } else {
            int rank = (int)(g_mom[r * 4 + 0] + 0.5f);
            c1  += (rank < 1);
            c5  += (rank < 5);
            c10 += (rank < 10);
            c20 += (rank < 20);
        }
    }
    __shared__ float sm[256];
    float vals[5] = {loss, c1, c5, c10, c20};
    float tot[5];
#pragma unroll
    for (int q = 0; q < 5; q++) {
        sm[tid] = vals[q];
        __syncthreads();
        for (int s = 128; s; s >>= 1) {
            if (tid < s) sm[tid] += sm[tid + s];
            __syncthreads();
        }
        tot[q] = sm[0];
        __syncthreads();
    }
    if (tid == 0) {
        out[0] = tot[0] / (float)(B_ * LOSS_T);  // mean over 1856
        out[1] = tot[1];
        out[2] = tot[2];
        out[3] = tot[3];
        out[4] = tot[4];
        out[5] = (float)(B_ * 3);                // count = 192
    }
}

// ---------------- launch ----------------
extern "C" void kernel_launch(void* const* d_in, const int* in_sizes, int n_in,
                              void* d_out, int out_size) {
    const int*   user   = (const int*)  d_in[0];
    const int*   venue  = (const int*)  d_in[1];
    const float* time   = (const float*)d_in[2];
    const float* vt     = (const float*)d_in[3];
    const float* ut     = (const float*)d_in[4];
    const float* w1     = (const float*)d_in[5];
    const float* b1     = (const float*)d_in[6];
    const float* w2     = (const float*)d_in[7];
    const float* b2     = (const float*)d_in[8];
    const float* Wih    = (const float*)d_in[9];
    const float* Whh    = (const float*)d_in[10];
    const float* bih    = (const float*)d_in[11];
    const float* bhh    = (const float*)d_in[12];
    float* out = (float*)d_out;

    k_embed<<<R_, THID>>>(time, venue, vt, w1, b1, w2, b2);
    k_rnn<<<B_, D_>>>(user, ut, Wih, Whh, bih, bhh);
    k_target<<<R_, D_>>>(venue, vt);
    dim3 g4(NVCH, B_), b4(32, 8);
    k_main<<<g4, b4>>>(vt, venue);
    k_final<<<1, 256>>>(out);
}

// round 4
// speedup vs baseline: 2.3712x; 2.3712x over previous
#include <cuda_runtime.h>
#include <cuda_bf16.h>

// Problem constants
#define B_   64
#define L_   32
#define D_   64
#define V_   100000
#define TIN  8
#define THID 128
#define R_   2048          // B*L rows
#define LOSS_T 29          // t < 29 -> loss rows, t >= 29 -> topk rows

// ---------------- scratch (__device__ globals: allowed) ----------------
__device__ float g_time_emb[R_ * D_];
__device__ float g_x[R_ * D_];
__device__ float g_seq[R_ * D_];
__device__ float g_lt[R_];
__device__ float g_mom[R_ * 4];           // loss rows: m1,m2 ; topk rows: slot0 = gt-count
__device__ float g_vtT[D_ * V_];          // venue table transposed [k][v], 25.6 MB

// ---------------- fast exp on FMA pipe ----------------
__device__ __forceinline__ float fexp(float x) {
    float t = x * 1.4426950408889634f;
    float z = t + 12582912.0f;                 // round-to-nearest via magic add
    int   n = __float_as_int(z) - 0x4B400000;
    float r = t - (z - 12582912.0f);           // r in [-0.5, 0.5]
    float p = fmaf(1.5403530e-4f, r, 1.3333558e-3f);
    p = fmaf(p, r, 9.6181291e-3f);
    p = fmaf(p, r, 5.5504109e-2f);
    p = fmaf(p, r, 2.4022651e-1f);
    p = fmaf(p, r, 6.9314718e-1f);
    p = fmaf(p, r, 1.0f);
    return __int_as_float((n + 127) << 23) * p;
}

__device__ __forceinline__ void ffma2(unsigned long long& d,
                                      unsigned long long a,
                                      unsigned long long b) {
    asm("fma.rn.f32x2 %0, %1, %2, %0;" : "+l"(d) : "l"(a), "l"(b));
}

__device__ __forceinline__ unsigned smem_u32(const void* p) {
    return (unsigned)__cvta_generic_to_shared(p);
}

// ---------------- K0: transpose venue_table -> g_vtT [k][v] ----------------
__global__ void k_transpose(const float* __restrict__ vt) {
    __shared__ float s[D_ * 33];            // [k][vl] padded
    const int tx = threadIdx.x;             // 0..31
    const int ty = threadIdx.y;             // 0..7
    const int tid = ty * 32 + tx;
    const int v0 = blockIdx.x * 32;         // 3125 blocks, exact
    // coalesced read of 32 venue rows (2048 floats)
#pragma unroll
    for (int i = 0; i < 8; i++) {
        int off = tid + i * 256;            // 0..2047
        int vl = off >> 6;
        int k  = off & 63;
        s[k * 33 + vl] = vt[v0 * 64 + off];
    }
    __syncthreads();
    // coalesced write of transposed
#pragma unroll
    for (int i = 0; i < 8; i++) {
        int k = i * 8 + ty;
        g_vtT[(size_t)k * V_ + v0 + tx] = s[k * 33 + tx];
    }
}

// ---------------- K1: time MLP + venue gather -> time_emb, x ----------------
__global__ void k_embed(const float* __restrict__ time, const int* __restrict__ venue,
                        const float* __restrict__ vt,
                        const float* __restrict__ w1, const float* __restrict__ b1,
                        const float* __restrict__ w2, const float* __restrict__ b2) {
    int row = blockIdx.x;          // 0..2047
    int tid = threadIdx.x;         // 0..127
    __shared__ float ts[TIN];
    __shared__ float hid[THID];
    if (tid < TIN) ts[tid] = time[row * TIN + tid];
    __syncthreads();
    float a = b1[tid];
#pragma unroll
    for (int k = 0; k < TIN; k++) a = fmaf(ts[k], w1[k * THID + tid], a);
    hid[tid] = fmaxf(a, 0.f);
    __syncthreads();
    if (tid < D_) {
        float te = b2[tid];
#pragma unroll 16
        for (int j = 0; j < THID; j++) te = fmaf(hid[j], w2[j * D_ + tid], te);
        g_time_emb[row * D_ + tid] = te;
        int vv = venue[row];
        g_x[row * D_ + tid] = vt[vv * D_ + tid] + te;
    }
}

// ---------------- K2: RNN over all 32 steps -> g_seq (h_before - time_emb) ----------------
__global__ void k_rnn(const int* __restrict__ user, const float* __restrict__ user_table,
                      const float* __restrict__ Wih, const float* __restrict__ Whh,
                      const float* __restrict__ bih, const float* __restrict__ bhh) {
    int b = blockIdx.x;            // 0..63
    int tid = threadIdx.x;         // 0..63
    __shared__ float WihT[D_ * D_];
    __shared__ float WhhT[D_ * D_];
    __shared__ float h[D_];
    __shared__ float xs[D_];
    for (int i = 0; i < D_; i++) {
        WihT[i * D_ + tid] = Wih[tid * D_ + i];
        WhhT[i * D_ + tid] = Whh[tid * D_ + i];
    }
    h[tid] = user_table[user[b] * D_ + tid];
    float bias = bih[tid] + bhh[tid];
    __syncthreads();
    for (int t = 0; t < L_; t++) {
        int r = b * L_ + t;
        g_seq[r * D_ + tid] = h[tid] - g_time_emb[r * D_ + tid];
        xs[tid] = g_x[r * D_ + tid];
        __syncthreads();
        float a = bias;
#pragma unroll 16
        for (int k = 0; k < D_; k++)
            a = fmaf(xs[k], WihT[k * D_ + tid], fmaf(h[k], WhhT[k * D_ + tid], a));
        __syncthreads();
        h[tid] = tanhf(a);
        __syncthreads();
    }
}

// ---------------- K3: target logits + zero moments ----------------
__global__ void k_target(const int* __restrict__ venue, const float* __restrict__ vt) {
    int r = blockIdx.x;            // 0..2047
    int tid = threadIdx.x;         // 0..63
    if (tid < 4) g_mom[r * 4 + tid] = 0.f;
    int tgt = venue[r];
    float v = g_seq[r * D_ + tid] * vt[tgt * D_ + tid];
#pragma unroll
    for (int o = 16; o; o >>= 1) v += __shfl_down_sync(0xffffffffu, v, o);
    __shared__ float p2[2];
    if ((tid & 31) == 0) p2[tid >> 5] = v;
    __syncthreads();
    if (tid == 0) g_lt[r] = p2[0] + p2[1];
}

// ---------------- K4: main pass — fused GEMM + softmax moments + rank counts ----------------
#define VT 128
#define VCHUNK 4352            // 34 tiles of 128
#define NVCH 23                // ceil(100000/4352)

__global__ void __launch_bounds__(256, 2)
k_main(const int* __restrict__ venue) {
    __shared__ __align__(16) float  venT[D_ * VT];       // [k][v]  32 KB
    __shared__ __align__(16) float2 seqDup[D_ * 32];     // [k][r] dup  16 KB  (total 48 KB)
    const int tx  = threadIdx.x;      // 0..31
    const int ty  = threadIdx.y;      // 0..7
    const int tid = ty * 32 + tx;
    const int row0 = blockIdx.y * 32;                     // one batch b
    const int vstart = blockIdx.x * VCHUNK;
    const int vend   = min(V_, vstart + VCHUNK);

    // load seq tile (k-major, duplicated pairs for f32x2)
    for (int e = tid; e < D_ * 32; e += 256) {
        int r = e & 31, k = e >> 5;
        float s = g_seq[(row0 + r) * D_ + k];
        seqDup[k * 32 + r] = make_float2(s, s);
    }
    // per-row metadata (4 rows per thread: t = 4*ty + i)
    float thr[4]; int tgtv[4]; bool istop[4];
    float mom[4][2]; float cnt[4];
#pragma unroll
    for (int i = 0; i < 4; i++) {
        int t = 4 * ty + i;
        int r = row0 + t;
        thr[i] = g_lt[r]; tgtv[i] = venue[r]; istop[i] = (t >= LOSS_T);
        mom[i][0] = mom[i][1] = 0.f; cnt[i] = 0.f;
    }
    __syncthreads();

    const ulonglong2* venp = reinterpret_cast<const ulonglong2*>(venT);
    const ulonglong2* seqp = reinterpret_cast<const ulonglong2*>(seqDup);

    for (int vbase = vstart; vbase < vend; vbase += VT) {
        // ---- coalesced async tile load from transposed table ----
        // 2048 float4s: f = tid + i*256 ; k = f>>5 ; vl4 = f&31
#pragma unroll
        for (int i = 0; i < 8; i++) {
            int f = tid + i * 256;
            int k   = f >> 5;
            int vl4 = f & 31;
            int v = vbase + vl4 * 4;
            float* dst = venT + k * VT + vl4 * 4;
            if (v < V_) {   // V_ % 4 == 0 so float4 granularity is safe
                const float* src = g_vtT + (size_t)k * V_ + v;
                unsigned da = smem_u32(dst);
                asm volatile("cp.async.cg.shared.global [%0], [%1], 16;"
                             :: "r"(da), "l"(src) : "memory");
            } else {
                *reinterpret_cast<float4*>(dst) = make_float4(0.f, 0.f, 0.f, 0.f);
            }
        }
        asm volatile("cp.async.commit_group;" ::: "memory");
        asm volatile("cp.async.wait_group 0;" ::: "memory");
        __syncthreads();

        unsigned long long acc[4][2];
#pragma unroll
        for (int i = 0; i < 4; i++) { acc[i][0] = 0ull; acc[i][1] = 0ull; }

#pragma unroll 16
        for (int k = 0; k < D_; k++) {
            ulonglong2 vv = venp[k * 32 + tx];            // venues 4tx..4tx+3 (2 pairs)
            ulonglong2 sA = seqp[k * 16 + 2 * ty];        // rows 4ty, 4ty+1 (dup)
            ulonglong2 sB = seqp[k * 16 + 2 * ty + 1];    // rows 4ty+2, 4ty+3 (dup)
            ffma2(acc[0][0], sA.x, vv.x); ffma2(acc[0][1], sA.x, vv.y);
            ffma2(acc[1][0], sA.y, vv.x); ffma2(acc[1][1], sA.y, vv.y);
            ffma2(acc[2][0], sB.x, vv.x); ffma2(acc[2][1], sB.x, vv.y);
            ffma2(acc[3][0], sB.y, vv.x); ffma2(acc[3][1], sB.y, vv.y);
        }

        int v0 = vbase + 4 * tx;
#pragma unroll
        for (int i = 0; i < 4; i++) {
            float l[4];
            l[0] = __uint_as_float((unsigned)(acc[i][0]));
            l[1] = __uint_as_float((unsigned)(acc[i][0] >> 32));
            l[2] = __uint_as_float((unsigned)(acc[i][1]));
            l[3] = __uint_as_float((unsigned)(acc[i][1] >> 32));
            if (istop[i]) {
#pragma unroll
                for (int j = 0; j < 4; j++)
                    if (v0 + j < V_ && v0 + j != tgtv[i] && l[j] > thr[i]) cnt[i] += 1.f;
            } else {
#pragma unroll
                for (int j = 0; j < 4; j++) {
                    if (v0 + j < V_) {
                        float e1 = fexp(l[j]);
                        mom[i][0] += e1;
                        mom[i][1] = fmaf(e1, e1, mom[i][1]);
                    }
                }
            }
        }
        __syncthreads();
    }

    // warp reduce (all lanes of a warp share the same 4 rows)
#pragma unroll
    for (int i = 0; i < 4; i++) {
        float m0 = mom[i][0], m1 = mom[i][1], c = cnt[i];
#pragma unroll
        for (int o = 16; o; o >>= 1) {
            m0 += __shfl_down_sync(0xffffffffu, m0, o);
            m1 += __shfl_down_sync(0xffffffffu, m1, o);
            c  += __shfl_down_sync(0xffffffffu, c,  o);
        }
        if (tx == 0) {
            int r = row0 + 4 * ty + i;
            if (istop[i]) {
                atomicAdd(&g_mom[r * 4 + 0], c);
            } else {
                atomicAdd(&g_mom[r * 4 + 0], m0);
                atomicAdd(&g_mom[r * 4 + 1], m1);
            }
        }
    }
}

// ---------------- K5: finalize loss + counts ----------------
__global__ void k_final(float* __restrict__ out) {
    int tid = threadIdx.x;   // 256
    float loss = 0.f, c1 = 0.f, c5 = 0.f, c10 = 0.f, c20 = 0.f;
    for (int r = tid; r < R_; r += 256) {
        int t = r & 31;
        if (t < LOSS_T) {
            float s1 = g_mom[r * 4 + 0];
            float m2 = g_mom[r * 4 + 1];
            float pt = fexp(g_lt[r]) / s1;
            float is1 = 1.f / s1;
            // sum_v exp(p_v) = V + 1 + m2/(2 s1^2) + O(m3/6 s1^3 ~ 1e-9 rel)
            float S = (float)V_ + 1.0f + m2 * is1 * is1 * 0.5f;
            loss += (logf(S) - pt);
        } else {
            int rank = (int)(g_mom[r * 4 + 0] + 0.5f);
            c1  += (rank < 1);
            c5  += (rank < 5);
            c10 += (rank < 10);
            c20 += (rank < 20);
        }
    }
    __shared__ float sm[256];
    float vals[5] = {loss, c1, c5, c10, c20};
    float tot[5];
#pragma unroll
    for (int q = 0; q < 5; q++) {
        sm[tid] = vals[q];
        __syncthreads();
        for (int s = 128; s; s >>= 1) {
            if (tid < s) sm[tid] += sm[tid + s];
            __syncthreads();
        }
        tot[q] = sm[0];
        __syncthreads();
    }
    if (tid == 0) {
        out[0] = tot[0] / (float)(B_ * LOSS_T);  // mean over 1856
        out[1] = tot[1];
        out[2] = tot[2];
        out[3] = tot[3];
        out[4] = tot[4];
        out[5] = (float)(B_ * 3);                // count = 192
    }
}

// ---------------- launch ----------------
extern "C" void kernel_launch(void* const* d_in, const int* in_sizes, int n_in,
                              void* d_out, int out_size) {
    const int*   user   = (const int*)  d_in[0];
    const int*   venue  = (const int*)  d_in[1];
    const float* time   = (const float*)d_in[2];
    const float* vt     = (const float*)d_in[3];
    const float* ut     = (const float*)d_in[4];
    const float* w1     = (const float*)d_in[5];
    const float* b1     = (const float*)d_in[6];
    const float* w2     = (const float*)d_in[7];
    const float* b2     = (const float*)d_in[8];
    const float* Wih    = (const float*)d_in[9];
    const float* Whh    = (const float*)d_in[10];
    const float* bih    = (const float*)d_in[11];
    const float* bhh    = (const float*)d_in[12];
    float* out = (float*)d_out;

    dim3 bt(32, 8);
    k_transpose<<<V_ / 32, bt>>>(vt);
    k_embed<<<R_, THID>>>(time, venue, vt, w1, b1, w2, b2);
    k_rnn<<<B_, D_>>>(user, ut, Wih, Whh, bih, bhh);
    k_target<<<R_, D_>>>(venue, vt);
    dim3 g4(NVCH, B_), b4(32, 8);
    k_main<<<g4, b4>>>(venue);
    k_final<<<1, 256>>>(out);
}

// round 5
// speedup vs baseline: 2.8092x; 1.1847x over previous
#include <cuda_runtime.h>
#include <cuda_bf16.h>

// Problem constants
#define B_   64
#define L_   32
#define D_   64
#define V_   100000
#define TIN  8
#define THID 128
#define R_   2048          // B*L rows
#define LOSS_T 29          // t < 29 -> loss rows, t >= 29 -> topk rows

// ---------------- scratch (__device__ globals: allowed) ----------------
__device__ float g_time_emb[R_ * D_];
__device__ float g_x[R_ * D_];
__device__ float g_seq[R_ * D_];
__device__ float g_lt[R_];
__device__ float g_mom[R_ * 4];           // loss rows: s1 ; topk rows: gt-count
__device__ float g_vtT[D_ * V_];          // venue table transposed [k][v], 25.6 MB

// ---------------- fast exp on FMA pipe ----------------
__device__ __forceinline__ float fexp(float x) {
    float t = x * 1.4426950408889634f;
    float z = t + 12582912.0f;                 // round-to-nearest via magic add
    int   n = __float_as_int(z) - 0x4B400000;
    float r = t - (z - 12582912.0f);           // r in [-0.5, 0.5]
    float p = fmaf(1.5403530e-4f, r, 1.3333558e-3f);
    p = fmaf(p, r, 9.6181291e-3f);
    p = fmaf(p, r, 5.5504109e-2f);
    p = fmaf(p, r, 2.4022651e-1f);
    p = fmaf(p, r, 6.9314718e-1f);
    p = fmaf(p, r, 1.0f);
    return __int_as_float((n + 127) << 23) * p;
}

__device__ __forceinline__ void ffma2(unsigned long long& d,
                                      unsigned long long a,
                                      unsigned long long b) {
    asm("fma.rn.f32x2 %0, %1, %2, %0;" : "+l"(d) : "l"(a), "l"(b));
}

__device__ __forceinline__ unsigned smem_u32(const void* p) {
    return (unsigned)__cvta_generic_to_shared(p);
}

// ---------------- K0: transpose venue_table -> g_vtT [k][v] ----------------
__global__ void k_transpose(const float* __restrict__ vt) {
    __shared__ float s[D_ * 33];            // [k][vl] padded
    const int tx = threadIdx.x;             // 0..31
    const int ty = threadIdx.y;             // 0..7
    const int tid = ty * 32 + tx;
    const int v0 = blockIdx.x * 32;         // 3125 blocks, exact
#pragma unroll
    for (int i = 0; i < 8; i++) {
        int off = tid + i * 256;            // 0..2047
        int vl = off >> 6;
        int k  = off & 63;
        s[k * 33 + vl] = vt[v0 * 64 + off];
    }
    __syncthreads();
#pragma unroll
    for (int i = 0; i < 8; i++) {
        int k = i * 8 + ty;
        g_vtT[(size_t)k * V_ + v0 + tx] = s[k * 33 + tx];
    }
}

// ---------------- K1: time MLP + venue gather -> time_emb, x ----------------
__global__ void k_embed(const float* __restrict__ time, const int* __restrict__ venue,
                        const float* __restrict__ vt,
                        const float* __restrict__ w1, const float* __restrict__ b1,
                        const float* __restrict__ w2, const float* __restrict__ b2) {
    int row = blockIdx.x;          // 0..2047
    int tid = threadIdx.x;         // 0..127
    __shared__ float ts[TIN];
    __shared__ float hid[THID];
    if (tid < TIN) ts[tid] = time[row * TIN + tid];
    __syncthreads();
    float a = b1[tid];
#pragma unroll
    for (int k = 0; k < TIN; k++) a = fmaf(ts[k], w1[k * THID + tid], a);
    hid[tid] = fmaxf(a, 0.f);
    __syncthreads();
    if (tid < D_) {
        float te = b2[tid];
#pragma unroll 16
        for (int j = 0; j < THID; j++) te = fmaf(hid[j], w2[j * D_ + tid], te);
        g_time_emb[row * D_ + tid] = te;
        int vv = venue[row];
        g_x[row * D_ + tid] = vt[vv * D_ + tid] + te;
    }
}

// ---------------- K2: RNN over all 32 steps -> g_seq (h_before - time_emb) ----------------
__global__ void k_rnn(const int* __restrict__ user, const float* __restrict__ user_table,
                      const float* __restrict__ Wih, const float* __restrict__ Whh,
                      const float* __restrict__ bih, const float* __restrict__ bhh) {
    int b = blockIdx.x;            // 0..63
    int tid = threadIdx.x;         // 0..63
    __shared__ float WihT[D_ * D_];
    __shared__ float WhhT[D_ * D_];
    __shared__ float h[D_];
    __shared__ float xs[D_];
    for (int i = 0; i < D_; i++) {
        WihT[i * D_ + tid] = Wih[tid * D_ + i];
        WhhT[i * D_ + tid] = Whh[tid * D_ + i];
    }
    h[tid] = user_table[user[b] * D_ + tid];
    float bias = bih[tid] + bhh[tid];
    __syncthreads();
    for (int t = 0; t < L_; t++) {
        int r = b * L_ + t;
        g_seq[r * D_ + tid] = h[tid] - g_time_emb[r * D_ + tid];
        xs[tid] = g_x[r * D_ + tid];
        __syncthreads();
        float a = bias;
#pragma unroll 16
        for (int k = 0; k < D_; k++)
            a = fmaf(xs[k], WihT[k * D_ + tid], fmaf(h[k], WhhT[k * D_ + tid], a));
        __syncthreads();
        h[tid] = tanhf(a);
        __syncthreads();
    }
}

// ---------------- K3: target logits + zero stats ----------------
__global__ void k_target(const int* __restrict__ venue, const float* __restrict__ vt) {
    int r = blockIdx.x;            // 0..2047
    int tid = threadIdx.x;         // 0..63
    if (tid < 4) g_mom[r * 4 + tid] = 0.f;
    int tgt = venue[r];
    float v = g_seq[r * D_ + tid] * vt[tgt * D_ + tid];
#pragma unroll
    for (int o = 16; o; o >>= 1) v += __shfl_down_sync(0xffffffffu, v, o);
    __shared__ float p2[2];
    if ((tid & 31) == 0) p2[tid >> 5] = v;
    __syncthreads();
    if (tid == 0) g_lt[r] = p2[0] + p2[1];
}

// ---------------- K4: main pass — fused GEMM + softmax s1 + rank counts ----------------
// Register tile: 4 venues x 8 rows per thread. Block (32,4)=128 thr, 4 blocks/SM.
#define VT 128
#define VCHUNK 4352            // 34 tiles of 128
#define NVCH 23                // ceil(100000/4352)

__global__ void __launch_bounds__(128, 4)
k_main(const int* __restrict__ venue) {
    __shared__ __align__(16) float  venT[D_ * VT];       // [k][v]  32 KB
    __shared__ __align__(16) float2 seqDup[D_ * 32];     // [k][r] dup  16 KB  (48 KB total)
    const int tx  = threadIdx.x;      // 0..31 -> 4 venues each
    const int ty  = threadIdx.y;      // 0..3  -> 8 rows each (rows 8ty..8ty+7)
    const int tid = ty * 32 + tx;
    const int row0 = blockIdx.y * 32;                     // one batch b
    const int vstart = blockIdx.x * VCHUNK;
    const int vend   = min(V_, vstart + VCHUNK);

    // load seq tile (k-major, duplicated pairs for f32x2)
    for (int e = tid; e < D_ * 32; e += 128) {
        int r = e & 31, k = e >> 5;
        float s = g_seq[(row0 + r) * D_ + k];
        seqDup[k * 32 + r] = make_float2(s, s);
    }
    // per-row metadata + running stat (s1 for loss rows, count for topk rows)
    float thr[8]; int tgtv[8]; float stat[8];
#pragma unroll
    for (int i = 0; i < 8; i++) {
        int r = row0 + ty * 8 + i;
        thr[i] = g_lt[r]; tgtv[i] = venue[r]; stat[i] = 0.f;
    }
    __syncthreads();

    const ulonglong2* venp = reinterpret_cast<const ulonglong2*>(venT);
    const ulonglong2* seqp = reinterpret_cast<const ulonglong2*>(seqDup);

    for (int vbase = vstart; vbase < vend; vbase += VT) {
        // ---- coalesced async tile load from transposed table ----
#pragma unroll
        for (int i = 0; i < 16; i++) {
            int f = tid + i * 128;          // 0..2047 float4 slots
            int k   = f >> 5;
            int vl4 = f & 31;
            int v = vbase + vl4 * 4;
            float* dst = venT + k * VT + vl4 * 4;
            if (v < V_) {   // V_ % 4 == 0 so float4 granularity is safe
                const float* src = g_vtT + (size_t)k * V_ + v;
                unsigned da = smem_u32(dst);
                asm volatile("cp.async.cg.shared.global [%0], [%1], 16;"
                             :: "r"(da), "l"(src) : "memory");
            } else {
                *reinterpret_cast<float4*>(dst) = make_float4(0.f, 0.f, 0.f, 0.f);
            }
        }
        asm volatile("cp.async.commit_group;" ::: "memory");
        asm volatile("cp.async.wait_group 0;" ::: "memory");
        __syncthreads();

        unsigned long long acc[8][2];
#pragma unroll
        for (int i = 0; i < 8; i++) { acc[i][0] = 0ull; acc[i][1] = 0ull; }

#pragma unroll 16
        for (int k = 0; k < D_; k++) {
            ulonglong2 vv = venp[k * 32 + tx];            // venues 4tx..4tx+3 (2 pairs)
#pragma unroll
            for (int j = 0; j < 4; j++) {
                ulonglong2 s = seqp[k * 16 + 4 * ty + j]; // rows 8ty+2j, 8ty+2j+1 (dup)
                ffma2(acc[2*j  ][0], s.x, vv.x); ffma2(acc[2*j  ][1], s.x, vv.y);
                ffma2(acc[2*j+1][0], s.y, vv.x); ffma2(acc[2*j+1][1], s.y, vv.y);
            }
        }

        int v0 = vbase + 4 * tx;
#pragma unroll
        for (int i = 0; i < 8; i++) {
            float l[4];
            l[0] = __uint_as_float((unsigned)(acc[i][0]));
            l[1] = __uint_as_float((unsigned)(acc[i][0] >> 32));
            l[2] = __uint_as_float((unsigned)(acc[i][1]));
            l[3] = __uint_as_float((unsigned)(acc[i][1] >> 32));
            if (ty * 8 + i >= LOSS_T) {                   // topk row: rank count
#pragma unroll
                for (int j = 0; j < 4; j++)
                    if (v0 + j < V_ && v0 + j != tgtv[i] && l[j] > thr[i]) stat[i] += 1.f;
            } else {                                      // loss row: s1 only
#pragma unroll
                for (int j = 0; j < 4; j++)
                    if (v0 + j < V_) stat[i] += fexp(l[j]);
            }
        }
        __syncthreads();
    }

    // warp reduce (all lanes of a warp share the same 8 rows)
#pragma unroll
    for (int i = 0; i < 8; i++) {
        float s = stat[i];
#pragma unroll
        for (int o = 16; o; o >>= 1) s += __shfl_down_sync(0xffffffffu, s, o);
        if (tx == 0) atomicAdd(&g_mom[(row0 + ty * 8 + i) * 4], s);
    }
}

// ---------------- K5: finalize loss + counts ----------------
__global__ void k_final(float* __restrict__ out) {
    int tid = threadIdx.x;   // 256
    float loss = 0.f, c1 = 0.f, c5 = 0.f, c10 = 0.f, c20 = 0.f;
    const float logS = logf((float)V_ + 1.0f);   // Σv exp(p_v) = V+1 (+ <=0.5 -> <=5e-6 abs)
    for (int r = tid; r < R_; r += 256) {
        int t = r & 31;
        if (t < LOSS_T) {
            float s1 = g_mom[r * 4 + 0];
            float pt = fexp(g_lt[r]) / s1;
            loss += (logS - pt);
        } else {
            int rank = (int)(g_mom[r * 4 + 0] + 0.5f);
            c1  += (rank < 1);
            c5  += (rank < 5);
            c10 += (rank < 10);
            c20 += (rank < 20);
        }
    }
    __shared__ float sm[256];
    float vals[5] = {loss, c1, c5, c10, c20};
    float tot[5];
#pragma unroll
    for (int q = 0; q < 5; q++) {
        sm[tid] = vals[q];
        __syncthreads();
        for (int s = 128; s; s >>= 1) {
            if (tid < s) sm[tid] += sm[tid + s];
            __syncthreads();
        }
        tot[q] = sm[0];
        __syncthreads();
    }
    if (tid == 0) {
        out[0] = tot[0] / (float)(B_ * LOSS_T);  // mean over 1856
        out[1] = tot[1];
        out[2] = tot[2];
        out[3] = tot[3];
        out[4] = tot[4];
        out[5] = (float)(B_ * 3);                // count = 192
    }
}

// ---------------- launch ----------------
extern "C" void kernel_launch(void* const* d_in, const int* in_sizes, int n_in,
                              void* d_out, int out_size) {
    const int*   user   = (const int*)  d_in[0];
    const int*   venue  = (const int*)  d_in[1];
    const float* time   = (const float*)d_in[2];
    const float* vt     = (const float*)d_in[3];
    const float* ut     = (const float*)d_in[4];
    const float* w1     = (const float*)d_in[5];
    const float* b1     = (const float*)d_in[6];
    const float* w2     = (const float*)d_in[7];
    const float* b2     = (const float*)d_in[8];
    const float* Wih    = (const float*)d_in[9];
    const float* Whh    = (const float*)d_in[10];
    const float* bih    = (const float*)d_in[11];
    const float* bhh    = (const float*)d_in[12];
    float* out = (float*)d_out;

    dim3 bt(32, 8);
    k_transpose<<<V_ / 32, bt>>>(vt);
    k_embed<<<R_, THID>>>(time, venue, vt, w1, b1, w2, b2);
    k_rnn<<<B_, D_>>>(user, ut, Wih, Whh, bih, bhh);
    k_target<<<R_, D_>>>(venue, vt);
    dim3 g4(NVCH, B_), b4(32, 4);
    k_main<<<g4, b4>>>(venue);
    k_final<<<1, 256>>>(out);
}